// round 9
// baseline (speedup 1.0000x reference)
#include <cuda_runtime.h>
#include <math_constants.h>

// RoIPool: feature_map [B=2, H=50, W=50, C=256] f32, rpn_pred [B=2, N=128, 4] f32
// out [B, N, 7, 7, C] f32.
//   x1=(int)(W*p0); y1=(int)(H*p1); x2=(int)(W*p2); y2=(int)(H*p3)
//   sw=(x2-x1)/7; sh=(y2-y1)/7   (in [1,4] by input construction)
//   out[b,n,i,j,c] = max_{r<sh,t<sw} fm[b, y1+i*sh+r, x1+j*sw+t, c]
// Bounds: x1+7*sw-1 <= x2-1 <= 49 (same for y) -> reference clip is dead code.
//
// R9: STREAMING formulation. For fixed (b,n,i) the 7 bins' columns union to a
// CONTIGUOUS span [x1, x1+7*sw). CTA = (i,n,b), 128 threads = 2 row-slots x 64
// channel-threads. Slot s handles window rows r in {s, s+2} (covers sh<=4).
// Per row: fully-unrolled dense loop over 7*sw columns (sw compile-time via
// 4-way dispatch), k-th load feeds accumulator j=k/sw (compile-time) -> all
// ~28 LDG.128 independent, zero per-load index math, deep MLP. Slot partials
// combined through smem.

#define POOL 7
#define NROIS 128
#define BB 2
#define HH 50
#define WW 50
#define CC 256
#define C4 (CC / 4)   // 64 float4 per pixel
#define NBINS (POOL * POOL)

__device__ __forceinline__ void fmax4(float4& m, const float4 v) {
    m.x = fmaxf(m.x, v.x);
    m.y = fmaxf(m.y, v.y);
    m.z = fmaxf(m.z, v.z);
    m.w = fmaxf(m.w, v.w);
}

// Stream one window row: 7*SW contiguous float4 loads, k -> bin k/SW.
template<int SW>
__device__ __forceinline__ void stream_row(const float4* __restrict__ rowp,
                                           float4 acc[POOL]) {
    #pragma unroll
    for (int k = 0; k < POOL * SW; ++k) {
        const float4 v = __ldg(rowp + k * C4);
        fmax4(acc[k / SW], v);   // k/SW is a compile-time constant per k
    }
}

template<int SW>
__device__ __forceinline__ void stream_rows(const float4* __restrict__ base,
                                            int slot, int sh,
                                            float4 acc[POOL]) {
    // Slot s covers window rows {s, s+2} that are < sh (sh in [1,4]).
    if (slot < sh)
        stream_row<SW>(base + slot * (WW * C4), acc);
    if (slot + 2 < sh)
        stream_row<SW>(base + (slot + 2) * (WW * C4), acc);
}

__global__ __launch_bounds__(128, 8) void roi_pool_kernel(
    const float4* __restrict__ fm,     // [B*H*W*C4] float4
    const float4* __restrict__ rois,   // [B*N] float4 (x1,y1,x2,y2)
    float4*       __restrict__ out)    // [B*N*49*C4] float4
{
    __shared__ float4 part[POOL][C4];  // slot-1 partial maxima (7 KB)

    const int i    = blockIdx.x;               // pooled row 0..6
    const int n    = blockIdx.y;               // roi
    const int b    = blockIdx.z;               // batch
    const int slot = threadIdx.x >> 6;         // 0..1 (row slot)
    const int c4   = threadIdx.x & 63;         // 0..63 -> 4 channels

    const float4 rp = __ldg(rois + b * NROIS + n);
    const int x1 = (int)(WW * rp.x);
    const int y1 = (int)(HH * rp.y);
    const int sw = ((int)(WW * rp.z) - x1) / POOL;   // in [1,4]
    const int sh = ((int)(HH * rp.w) - y1) / POOL;   // in [1,4]

    // Base at (window row 0 of this bin-row, x1), channel quad c4.
    const float4* base = fm + ((b * HH + (y1 + i * sh)) * WW + x1) * C4 + c4;

    const float NEG = -CUDART_INF_F;
    float4 acc[POOL];
    #pragma unroll
    for (int j = 0; j < POOL; ++j) acc[j] = make_float4(NEG, NEG, NEG, NEG);

    // Warp-uniform 4-way dispatch on sw (compile-time span length).
    switch (sw) {
        case 1:  stream_rows<1>(base, slot, sh, acc); break;
        case 2:  stream_rows<2>(base, slot, sh, acc); break;
        case 3:  stream_rows<3>(base, slot, sh, acc); break;
        default: stream_rows<4>(base, slot, sh, acc); break;
    }

    // Combine the two slots' partials through smem; slot 0 stores.
    if (slot == 1) {
        #pragma unroll
        for (int j = 0; j < POOL; ++j) part[j][c4] = acc[j];
    }
    __syncthreads();
    if (slot == 0) {
        float4* obase = out + (((b * NROIS + n) * POOL + i) * POOL) * C4 + c4;
        #pragma unroll
        for (int j = 0; j < POOL; ++j) {
            float4 m = acc[j];
            fmax4(m, part[j][c4]);
            obase[j * C4] = m;
        }
    }
}

extern "C" void kernel_launch(void* const* d_in, const int* in_sizes, int n_in,
                              void* d_out, int out_size) {
    const float4* fm   = (const float4*)d_in[0];  // feature_map
    const float4* rois = (const float4*)d_in[1];  // rpn_pred as float4
    float4*       out  = (float4*)d_out;

    dim3 grid(POOL, NROIS, BB);                   // 7 x 128 x 2 = 1792 CTAs
    roi_pool_kernel<<<grid, 128>>>(fm, rois, out);
}

// round 10
// speedup vs baseline: 1.5731x; 1.5731x over previous
#include <cuda_runtime.h>
#include <math_constants.h>

// RoIPool: feature_map [B=2, H=50, W=50, C=256] f32, rpn_pred [B=2, N=128, 4] f32
// out [B, N, 7, 7, C] f32.
//   x1=(int)(W*p0); y1=(int)(H*p1); x2=(int)(W*p2); y2=(int)(H*p3)
//   sw=(x2-x1)/7; sh=(y2-y1)/7   (in [1,4] by input construction)
//   out[b,n,i,j,c] = max_{r<sh,t<sw} fm[b, y1+i*sh+r, x1+j*sw+t, c]
// Bounds: x1+7*sw-1 <= x2-1 <= 49 (same for y) -> reference clip is dead code.
//
// R10: 16 channels PER THREAD (4 float4 accumulators, stride-16 interleave so
// every load/store is 256B-contiguous across 16 lanes). 16 threads per bin ->
// warp = 2 bins of the SAME ROI (CTA-uniform (sh,sw) dispatch stays uniform).
// CTA = 160 threads = 5 warps = 10 bins; grid (5,128,2) = 1280 CTAs = 6400
// warps -> SINGLE WAVE at 9 CTAs/SM. One dependent chain per thread with ~25
// independent immediate-offset gathers (4x the MLP of earlier rounds).
// Bin 49 is a phantom (base aliased to bin 48, result not stored).

#define POOL 7
#define NROIS 128
#define BB 2
#define HH 50
#define WW 50
#define CC 256
#define C4 (CC / 4)   // 64 float4 per pixel
#define NBINS (POOL * POOL)       // 49
#define THREADS 160

__device__ __forceinline__ void fmax4(float4& m, const float4 v) {
    m.x = fmaxf(m.x, v.x);
    m.y = fmaxf(m.y, v.y);
    m.z = fmaxf(m.z, v.z);
    m.w = fmaxf(m.w, v.w);
}

// Exact SHxSW window, 4 float4 per cell, all offsets compile-time immediates.
template<int SH, int SW>
__device__ __forceinline__ void window16(const float4* __restrict__ base,
                                         float4 acc[4]) {
    #pragma unroll
    for (int r = 0; r < SH; ++r) {
        #pragma unroll
        for (int t = 0; t < SW; ++t) {
            const float4* cp = base + (r * WW + t) * C4;
            float4 v0 = __ldg(cp);
            float4 v1 = __ldg(cp + 16);
            float4 v2 = __ldg(cp + 32);
            float4 v3 = __ldg(cp + 48);
            fmax4(acc[0], v0);
            fmax4(acc[1], v1);
            fmax4(acc[2], v2);
            fmax4(acc[3], v3);
        }
    }
}

__global__ __launch_bounds__(THREADS, 9) void roi_pool_kernel(
    const float4* __restrict__ fm,     // [B*H*W*C4] float4
    const float4* __restrict__ rois,   // [B*N] float4 (x1,y1,x2,y2)
    float4*       __restrict__ out)    // [B*N*49*C4] float4
{
    const int warp = threadIdx.x >> 5;          // 0..4
    const int lane = threadIdx.x & 31;
    const int half = lane >> 4;                 // 0..1 -> which bin of the warp
    const int t16  = lane & 15;                 // 0..15 -> channel group

    const int n = blockIdx.y;
    const int b = blockIdx.z;

    const int bin  = blockIdx.x * 10 + warp * 2 + half;  // 0..49
    const bool valid = (bin < NBINS);
    const int binc = valid ? bin : (NBINS - 1);          // phantom -> alias 48

    const float4 rp = __ldg(rois + b * NROIS + n);
    const int x1 = (int)(WW * rp.x);
    const int y1 = (int)(HH * rp.y);
    const int sw = ((int)(WW * rp.z) - x1) / POOL;   // in [1,4]
    const int sh = ((int)(HH * rp.w) - y1) / POOL;   // in [1,4]

    const int i = binc / POOL;
    const int j = binc - i * POOL;

    // Thread covers float4 indices {t16, t16+16, t16+32, t16+48} of the pixel.
    const float4* base =
        fm + ((b * HH + (y1 + i * sh)) * WW + (x1 + j * sw)) * C4 + t16;

    const float NEG = -CUDART_INF_F;
    float4 acc[4];
    #pragma unroll
    for (int k = 0; k < 4; ++k) acc[k] = make_float4(NEG, NEG, NEG, NEG);

    // CTA-uniform 16-way dispatch on (sh,sw).
    const int code = (sh - 1) * 4 + (sw - 1);
    switch (code) {
        case  0: window16<1,1>(base, acc); break;
        case  1: window16<1,2>(base, acc); break;
        case  2: window16<1,3>(base, acc); break;
        case  3: window16<1,4>(base, acc); break;
        case  4: window16<2,1>(base, acc); break;
        case  5: window16<2,2>(base, acc); break;
        case  6: window16<2,3>(base, acc); break;
        case  7: window16<2,4>(base, acc); break;
        case  8: window16<3,1>(base, acc); break;
        case  9: window16<3,2>(base, acc); break;
        case 10: window16<3,3>(base, acc); break;
        case 11: window16<3,4>(base, acc); break;
        case 12: window16<4,1>(base, acc); break;
        case 13: window16<4,2>(base, acc); break;
        case 14: window16<4,3>(base, acc); break;
        default: window16<4,4>(base, acc); break;
    }

    if (valid) {
        float4* obase = out + ((b * NROIS + n) * NBINS + bin) * C4 + t16;
        obase[0]  = acc[0];
        obase[16] = acc[1];
        obase[32] = acc[2];
        obase[48] = acc[3];
    }
}

extern "C" void kernel_launch(void* const* d_in, const int* in_sizes, int n_in,
                              void* d_out, int out_size) {
    const float4* fm   = (const float4*)d_in[0];  // feature_map
    const float4* rois = (const float4*)d_in[1];  // rpn_pred as float4
    float4*       out  = (float4*)d_out;

    dim3 grid(5, NROIS, BB);                      // 5 x 128 x 2 = 1280 CTAs
    roi_pool_kernel<<<grid, THREADS>>>(fm, rois, out);
}